// round 15
// baseline (speedup 1.0000x reference)
#include <cuda_runtime.h>
#include <math.h>
#include <stdint.h>

#define BB    1024     // batch rows
#define NN    8192     // samples per row
#define MM2   900      // parity-fold period
#define MM3   486      // reflection-folded m range (451 used, padded to 9*54)
#define NB    140      // bpm bins
#define NBP   144      // padded bins
#define NCH   9        // m-chunks
#define CHM   54       // m per chunk (9*54 = 486)
#define SLAB  9        // m per smem slab (6 steps)

// ---------------- device scratch ----------------
__device__ float4 d_fold[(size_t)BB * MM3];             // (ve,ue,vo,uo) per (row,m)
__device__ float2 d_part[(size_t)BB * NCH * NBP];       // [row][chunk][bin] (S,C)
__device__ float  d_tl[BB];
__device__ float  d_fl[BB];
__device__ unsigned int d_done;

typedef unsigned long long ull;

// ---------------- f32x2 helpers ----------------
__device__ __forceinline__ ull pk2(float lo, float hi) {
    ull r;
    asm("mov.b64 %0, {%1, %2};" : "=l"(r) : "f"(lo), "f"(hi));
    return r;
}
__device__ __forceinline__ void upk2(float& lo, float& hi, ull v) {
    asm("mov.b64 {%0, %1}, %2;" : "=f"(lo), "=f"(hi) : "l"(v));
}
__device__ __forceinline__ void fma2(ull& d, ull a, ull b) {
    asm("fma.rn.f32x2 %0, %1, %2, %0;" : "+l"(d) : "l"(a), "l"(b));
}
__device__ __forceinline__ ull add2(ull a, ull b) {
    ull r;
    asm("add.rn.f32x2 %0, %1, %2;" : "=l"(r) : "l"(a), "l"(b));
    return r;
}
__device__ __forceinline__ ull mul2(ull a, ull b) {
    ull r;
    asm("mul.rn.f32x2 %0, %1, %2;" : "=l"(r) : "l"(a), "l"(b));
    return r;
}
__device__ __forceinline__ float sum2(ull v) {
    float lo, hi; upk2(lo, hi, v); return lo + hi;
}

// ---------------- warp helpers ----------------
__device__ __forceinline__ float wsum(float v) {
    #pragma unroll
    for (int o = 16; o; o >>= 1) v += __shfl_down_sync(0xffffffffu, v, o);
    return v;
}
__device__ __forceinline__ float wallsum(float v) {
    #pragma unroll
    for (int o = 16; o; o >>= 1) v += __shfl_xor_sync(0xffffffffu, v, o);
    return v;
}
__device__ __forceinline__ float wallmax(float v) {
    #pragma unroll
    for (int o = 16; o; o >>= 1) v = fmaxf(v, __shfl_xor_sync(0xffffffffu, v, o));
    return v;
}

// ---------------- K1: pearson + parity fold (f32x2-packed) + reflection ------
__global__ void __launch_bounds__(256) k_fold(const float* __restrict__ x,
                                              const float* __restrict__ y) {
    __shared__ float sge[MM2];
    __shared__ float sgo[MM2];
    __shared__ float red[8][5];
    int b = blockIdx.x;
    int tid = threadIdx.x;
    int lane = tid & 31, warp = tid >> 5;

    if (b == 0 && tid == 0) d_done = 0;    // ticket reset for this replay

    const float4* xr = (const float4*)(x + (size_t)b * NN);
    const float4* yr = (const float4*)(y + (size_t)b * NN);
    const float W = 3.8349520e-4f;          // pi/8191
    const ull NEG1 = pk2(-1.f, -1.f);

    ull ax0 = 0, ax1 = 0, ay0 = 0, ay1 = 0;
    ull axx0 = 0, axx1 = 0, ayy0 = 0, ayy1 = 0;
    ull axy0 = 0, axy1 = 0;
    ull ge0 = 0, ge1 = 0, go0 = 0, go1 = 0;

    if (tid < 225) {
        #pragma unroll
        for (int j = 0; j < 10; j++) {
            int q = tid + 225 * j;
            if (j < 9 || q < 2048) {
                float4 xv = xr[q];
                float4 yv = yr[q];
                ull xp0 = pk2(xv.x, xv.y), xp1 = pk2(xv.z, xv.w);
                ull yp0 = pk2(yv.x, yv.y), yp1 = pk2(yv.z, yv.w);
                ax0 = add2(ax0, xp0);  ax1 = add2(ax1, xp1);
                ay0 = add2(ay0, yp0);  ay1 = add2(ay1, yp1);
                fma2(axx0, xp0, xp0);  fma2(axx1, xp1, xp1);
                fma2(ayy0, yp0, yp0);  fma2(ayy1, yp1, yp1);
                fma2(axy0, xp0, yp0);  fma2(axy1, xp1, yp1);

                int n = 4 * q;
                float s0 = __sinf((float)(n)     * W);
                float s1 = __sinf((float)(n + 1) * W);
                float s2 = __sinf((float)(n + 2) * W);
                float s3 = __sinf((float)(n + 3) * W);
                ull sp0 = pk2(s0, s1), sp1 = pk2(s2, s3);
                sp0 = mul2(sp0, sp0);  sp1 = mul2(sp1, sp1);
                ull h0 = mul2(xp0, sp0), h1 = mul2(xp1, sp1);
                ge0 = add2(ge0, h0);  ge1 = add2(ge1, h1);
                if (j & 1) { fma2(go0, h0, NEG1); fma2(go1, h1, NEG1); }
                else       { go0 = add2(go0, h0); go1 = add2(go1, h1); }
            }
        }
        float g0, g1, g2, g3, o0, o1, o2, o3;
        upk2(g0, g1, ge0); upk2(g2, g3, ge1);
        upk2(o0, o1, go0); upk2(o2, o3, go1);
        sge[4 * tid]     = g0;  sgo[4 * tid]     = o0;
        sge[4 * tid + 1] = g1;  sgo[4 * tid + 1] = o1;
        sge[4 * tid + 2] = g2;  sgo[4 * tid + 2] = o2;
        sge[4 * tid + 3] = g3;  sgo[4 * tid + 3] = o3;
    }
    __syncthreads();

    for (int m = tid; m < MM3; m += 256) {
        float4 o;
        if (m == 0) {
            o = make_float4(sge[0], sge[0], sgo[0], sgo[0]);
        } else if (m < 450) {
            float a = sge[m], bb2 = sge[900 - m];
            float c = sgo[m], d  = sgo[900 - m];
            o = make_float4(a - bb2, a + bb2, c + d, c - d);
        } else if (m == 450) {
            o = make_float4(sge[450], sge[450], sgo[450], sgo[450]);
        } else {
            o = make_float4(0.f, 0.f, 0.f, 0.f);
        }
        d_fold[(size_t)b * MM3 + m] = o;
    }

    float sx = sum2(ax0) + sum2(ax1);
    float sy = sum2(ay0) + sum2(ay1);
    float sxx = sum2(axx0) + sum2(axx1);
    float syy = sum2(ayy0) + sum2(ayy1);
    float sxy = sum2(axy0) + sum2(axy1);

    sx = wsum(sx); sy = wsum(sy); sxy = wsum(sxy); sxx = wsum(sxx); syy = wsum(syy);
    if (lane == 0) { red[warp][0]=sx; red[warp][1]=sy; red[warp][2]=sxy; red[warp][3]=sxx; red[warp][4]=syy; }
    __syncthreads();
    if (tid == 0) {
        double SX=0, SY=0, SXY=0, SXX=0, SYY=0;
        #pragma unroll
        for (int w = 0; w < 8; w++) {
            SX += red[w][0]; SY += red[w][1]; SXY += red[w][2];
            SXX += red[w][3]; SYY += red[w][4];
        }
        double num = (double)NN * SXY - SX * SY;
        double den = sqrt(((double)NN * SXX - SX * SX) * ((double)NN * SYY - SY * SY));
        d_tl[b] = (float)(1.0 - num / den);
    }
}

// ---------------- K2: reflected parity NUDFT (R13 verbatim) ------------------
__global__ void __launch_bounds__(288, 2) k_dft() {
    __shared__ float sTab[SLAB * 2 * NBP];
    __shared__ ull   sGE[SLAB][32];
    __shared__ ull   sGO[SLAB][32];

    int tile  = blockIdx.x;
    int chunk = blockIdx.y;
    int tid = threadIdx.x;
    int tx = tid % 36;
    int ty = tid / 36;

    int rowBase = tile * 32;
    int mBase = chunk * CHM;

    int bk  = tid % NBP;
    int grp = tid / NBP;
    int freq = 40 + bk;

    ull acc[4][4] = {};
    const ull* gbase = (tx & 1) ? &sGO[0][0] : &sGE[0][0];
    const float ASCALE = 3.4906585e-3f;

    for (int step = 0; step < CHM / SLAB; step++) {
        int m0 = mBase + step * SLAB;
        __syncthreads();
        #pragma unroll
        for (int i = 0; i < 5; i++) {
            int mi = grp * 5 + i;
            if (mi < SLAB) {
                float s = 0.f, c = 0.f;
                if (bk < NB) {
                    int r = (freq * (m0 + mi)) % 1800;
                    if (r >= 900) r -= 1800;
                    __sincosf((float)r * ASCALE, &s, &c);
                }
                sTab[mi * (2 * NBP) + 2 * bk]     = s;
                sTab[mi * (2 * NBP) + 2 * bk + 1] = c;
            }
        }
        {
            int r = tid & 31, mi = tid >> 5;
            float4 v = d_fold[(size_t)(rowBase + r) * MM3 + m0 + mi];
            sGE[mi][r] = pk2(v.x, v.y);
            sGO[mi][r] = pk2(v.z, v.w);
        }
        __syncthreads();

        #pragma unroll
        for (int mi = 0; mi < SLAB; mi++) {
            const ull* gq = gbase + mi * 32 + 4 * ty;
            ull g0 = gq[0], g1 = gq[1], g2 = gq[2], g3 = gq[3];
            const ull* trow = (const ull*)&sTab[mi * (2 * NBP)];
            ull p0 = trow[tx];
            ull p1 = trow[tx + 36];
            ull p2 = trow[tx + 72];
            ull p3 = trow[tx + 108];
            fma2(acc[0][0], g0, p0); fma2(acc[0][1], g0, p1);
            fma2(acc[0][2], g0, p2); fma2(acc[0][3], g0, p3);
            fma2(acc[1][0], g1, p0); fma2(acc[1][1], g1, p1);
            fma2(acc[1][2], g1, p2); fma2(acc[1][3], g1, p3);
            fma2(acc[2][0], g2, p0); fma2(acc[2][1], g2, p1);
            fma2(acc[2][2], g2, p2); fma2(acc[2][3], g2, p3);
            fma2(acc[3][0], g3, p0); fma2(acc[3][1], g3, p1);
            fma2(acc[3][2], g3, p2); fma2(acc[3][3], g3, p3);
        }
    }

    #pragma unroll
    for (int r = 0; r < 4; r++) {
        int row = rowBase + 4 * ty + r;
        ull* dst = (ull*)(d_part + ((size_t)row * NCH + chunk) * NBP);
        dst[tx]       = acc[r][0];
        dst[tx + 36]  = acc[r][1];
        dst[tx + 72]  = acc[r][2];
        dst[tx + 108] = acc[r][3];
    }
}

// ---------------- K3: per-row loss + fused final scalar (ticket) -------------
#define LT 160   // threads (5 warps); bins 0..143 active
__global__ void __launch_bounds__(LT) k_loss(const int* __restrict__ hr,
                                             const int* __restrict__ epoch_p,
                                             float* __restrict__ out) {
    __shared__ float sh[8];
    __shared__ float shH;
    int tid = threadIdx.x;
    int lane = tid & 31, warp = tid >> 5;
    int row = blockIdx.x;
    bool valid = tid < NB;

    float s = 0.f, c = 0.f;
    if (valid) {
        const float2* pr = d_part + (size_t)row * NCH * NBP + tid;
        #pragma unroll
        for (int ch = 0; ch < NCH; ch++) {
            float2 v = pr[ch * NBP];
            s += v.x; c += v.y;
        }
    }
    float ca = valid ? (s * s + c * c) : 0.f;

    float v = wallsum(ca);
    if (lane == 0) sh[warp] = v;
    __syncthreads();
    float tot = sh[0] + sh[1] + sh[2] + sh[3] + sh[4];
    __syncthreads();

    float logit = ca / tot;

    v = wallmax(valid ? logit : -1e30f);
    if (lane == 0) sh[warp] = v;
    __syncthreads();
    float mx = fmaxf(fmaxf(fmaxf(sh[0], sh[1]), fmaxf(sh[2], sh[3])), sh[4]);
    __syncthreads();

    v = wallsum(valid ? expf(logit - mx) : 0.f);
    if (lane == 0) sh[warp] = v;
    __syncthreads();
    float lse = mx + logf(sh[0] + sh[1] + sh[2] + sh[3] + sh[4]);

    int h = hr[row];
    if (tid == h) shH = logit;
    __syncthreads();
    float ce = lse - shH;
    __syncthreads();

    float klc = 0.f;
    if (valid) {
        float dd = (float)tid - (float)h;
        float t = expf(-0.5f * dd * dd) * 0.3989422804014327f;
        t = fmaxf(t, 1e-15f);
        klc = expf(t) * (t - (logit - lse));
    }
    v = wallsum(klc);
    if (lane == 0) sh[warp] = v;
    __syncthreads();
    if (tid == 0) d_fl[row] = ce + (sh[0] + sh[1] + sh[2] + sh[3] + sh[4]) / (float)NB;

    // ---- ticket: last block computes the final scalar ----
    __threadfence();
    __syncthreads();
    __shared__ unsigned int sT;
    if (tid == 0) sT = atomicAdd(&d_done, 1u);
    __syncthreads();
    if (sT != (unsigned)(gridDim.x - 1)) return;
    __threadfence();

    float a = 0.f, cc = 0.f;
    #pragma unroll
    for (int i = 0; i < 7; i++) {           // 7*160 = 1120 >= 1024
        int idx = tid + 160 * i;
        if (idx < BB) { a += d_tl[idx]; cc += d_fl[idx]; }
    }
    a = wallsum(a); cc = wallsum(cc);
    __shared__ float sA[5], sC[5];
    if (lane == 0) { sA[warp] = a; sC[warp] = cc; }
    __syncthreads();
    if (tid == 0) {
        float TA = sA[0] + sA[1] + sA[2] + sA[3] + sA[4];
        float TC = sC[0] + sC[1] + sC[2] + sC[3] + sC[4];
        float tl = TA / (float)BB;
        float fl = TC / (float)BB;
        int epoch = epoch_p[0];
        float alpha, beta;
        if (epoch > 25) { alpha = 0.05f; beta = 2.0f; }
        else {
            float e = (float)epoch * 0.04f;
            alpha = 0.1f * exp2f(-e);
            beta  = exp2f(e);
        }
        out[0] = alpha * tl + beta * fl;
    }
}

// ---------------- launch ----------------
extern "C" void kernel_launch(void* const* d_in, const int* in_sizes, int n_in,
                              void* d_out, int out_size) {
    const int*   epoch_p = nullptr;
    const float* xp = nullptr;
    const float* yp = nullptr;
    const int*   hrp = nullptr;
    for (int i = 0; i < n_in; i++) {
        if (in_sizes[i] == 1 && !epoch_p) epoch_p = (const int*)d_in[i];
        else if (in_sizes[i] == BB * NN) { if (!xp) xp = (const float*)d_in[i]; else yp = (const float*)d_in[i]; }
        else if (in_sizes[i] == BB) hrp = (const int*)d_in[i];
    }
    float* out = (float*)d_out;

    k_fold<<<BB, 256>>>(xp, yp);
    k_dft<<<dim3(32, NCH), 288>>>();
    k_loss<<<BB, LT>>>(hrp, epoch_p, out);
    (void)out_size;
}